// round 11
// baseline (speedup 1.0000x reference)
#include <cuda_runtime.h>
#include <cuda_fp16.h>
#include <cstdint>

#define NN   100000
#define EE   3200000
#define FH   256
#define FIN  512
#define FOUT 64
#define HOPS 10
#define NH1  50048                     // first-half rows (128*391, divisible by 8)
#define GEMM_BLKS 782                  // 2 * 391 m-tiles for half A
#define SPMM_B_BLKS 6244               // ceil((NN-NH1)/8)
#define FUSED_GRID (GEMM_BLKS * 9)     // 7038

// ---------------- scratch (device globals) ----------------------------------
__device__ __half g_x16 [(size_t)NN * FIN];
__device__ __half g_x016[(size_t)NN * FH];
__device__ __half g_h16 [(size_t)NN * FH];
__device__ __half g_g16 [(size_t)NN * FH];   // ping-pong h
__device__ __half g_t16 [(size_t)NN * FH];
__device__ __half g_W1t [(size_t)FIN * FH];
__device__ __half g_W3p [(size_t)FH * FH];   // (W3 + I)^T, [n][k]
__device__ __half g_W2t [(size_t)FH * FOUT];
__device__ int    g_rowstart[NN + 1];
__device__ int    g_cnt[NN];
__device__ int2   g_epack[EE];

// ---------------- conversions ------------------------------------------------
__global__ void x2h_kernel(const float* __restrict__ x) {
    size_t i = (size_t)blockIdx.x * blockDim.x + threadIdx.x;
    if (i >= (size_t)NN * FIN / 8) return;
    float4 a = __ldg(((const float4*)x) + 2 * i);
    float4 b = __ldg(((const float4*)x) + 2 * i + 1);
    uint4 o;
    ((__half2*)&o)[0] = __floats2half2_rn(a.x, a.y);
    ((__half2*)&o)[1] = __floats2half2_rn(a.z, a.w);
    ((__half2*)&o)[2] = __floats2half2_rn(b.x, b.y);
    ((__half2*)&o)[3] = __floats2half2_rn(b.z, b.w);
    ((uint4*)g_x16)[i] = o;
}

__global__ void wt_kernel(const float* __restrict__ W, __half* __restrict__ Bt,
                          int K, int Nc, int addI) {
    int i = blockIdx.x * blockDim.x + threadIdx.x;
    if (i >= K * Nc) return;
    int n = i / K, k = i % K;
    float v = __ldg(&W[(size_t)k * Nc + n]);
    if (addI && k == n) v += 1.0f;
    Bt[i] = __float2half_rn(v);
}

// ---------------- CSR build --------------------------------------------------
__global__ void zero_cnt_kernel() {
    int i = blockIdx.x * blockDim.x + threadIdx.x;
    if (i < NN) g_cnt[i] = 0;
}

__global__ void hist_kernel(const int* __restrict__ erow) {
    int e = blockIdx.x * blockDim.x + threadIdx.x;
    if (e < EE) atomicAdd(&g_cnt[erow[e]], 1);
}

// exclusive scan; seeds g_cnt with offsets (scatter cursor)
__global__ void scan_kernel() {
    __shared__ int wsum[32];
    __shared__ int carry_s;
    int t = threadIdx.x, lane = t & 31, w = t >> 5;
    if (t == 0) carry_s = 0;
    __syncthreads();
    for (int base = 0; base < NN; base += 1024) {
        int i = base + t;
        int v = (i < NN) ? g_cnt[i] : 0;
        int s = v;
        #pragma unroll
        for (int off = 1; off < 32; off <<= 1) {
            int u = __shfl_up_sync(0xffffffff, s, off);
            if (lane >= off) s += u;
        }
        if (lane == 31) wsum[w] = s;
        __syncthreads();
        if (w == 0) {
            int ws = wsum[lane];
            #pragma unroll
            for (int off = 1; off < 32; off <<= 1) {
                int u = __shfl_up_sync(0xffffffff, ws, off);
                if (lane >= off) ws += u;
            }
            wsum[lane] = ws;
        }
        __syncthreads();
        int wpre = (w == 0) ? 0 : wsum[w - 1];
        if (i < NN) {
            int rs = carry_s + wpre + s - v;
            g_rowstart[i] = rs;
            g_cnt[i] = rs;
        }
        __syncthreads();
        if (t == 1023) carry_s += wsum[31];
        __syncthreads();
    }
    if (threadIdx.x == 0) g_rowstart[NN] = carry_s;
}

__global__ void scatter_kernel(const int* __restrict__ erow,
                               const int* __restrict__ ecol,
                               const float* __restrict__ eval) {
    int e = blockIdx.x * blockDim.x + threadIdx.x;
    if (e < EE) {
        int p = atomicAdd(&g_cnt[erow[e]], 1);
        g_epack[p] = make_int2(ecol[e], __float_as_int(eval[e]));
    }
}

// ---------------- SPMM body (R4 semantics) -------------------------------------
__device__ __forceinline__ void spmm_row(const __half* __restrict__ h,
                                         const float* __restrict__ A2,
                                         int row, int lane) {
    int s = g_rowstart[row];
    int e = g_rowstart[row + 1];
    float acc[8];
    #pragma unroll
    for (int q = 0; q < 8; q++) acc[q] = 0.f;

    #pragma unroll 4
    for (int p = s; p < e; ++p) {
        int2 ev = __ldg(&g_epack[p]);
        float v = __int_as_float(ev.y);
        uint4 raw = __ldg(((const uint4*)(h + (size_t)ev.x * FH)) + lane);
        const __half2* hh = (const __half2*)&raw;
        #pragma unroll
        for (int q = 0; q < 4; q++) {
            float2 f = __half22float2(hh[q]);
            acc[2 * q]     += v * f.x;
            acc[2 * q + 1] += v * f.y;
        }
    }
    float a = __ldg(&A2[row]);
    uint4 xraw = __ldg(((const uint4*)(g_x016 + (size_t)row * FH)) + lane);
    const __half2* xh = (const __half2*)&xraw;
    #pragma unroll
    for (int q = 0; q < 4; q++) {
        float2 f = __half22float2(xh[q]);
        acc[2 * q]     += a * f.x;
        acc[2 * q + 1] += a * f.y;
    }
    uint4 o;
    #pragma unroll
    for (int q = 0; q < 4; q++)
        ((__half2*)&o)[q] = __floats2half2_rn(acc[2 * q], acc[2 * q + 1]);
    ((uint4*)(g_t16 + (size_t)row * FH))[lane] = o;
}

// standalone SPMM over [row_off, row_end)
__global__ void spmm_kernel(const __half* __restrict__ h,
                            const float* __restrict__ A2,
                            int row_off, int row_end) {
    int row  = row_off + blockIdx.x * 8 + (threadIdx.x >> 5);
    if (row >= row_end) return;
    spmm_row(h, A2, row, threadIdx.x & 31);
}

// ---------------- GEMM bodies ---------------------------------------------------
__device__ __forceinline__ void mma_f16(float* d, const uint32_t* a, const uint32_t* b) {
    asm volatile(
        "mma.sync.aligned.m16n8k16.row.col.f32.f16.f16.f32 "
        "{%0,%1,%2,%3}, {%4,%5,%6,%7}, {%8,%9}, {%0,%1,%2,%3};\n"
        : "+f"(d[0]), "+f"(d[1]), "+f"(d[2]), "+f"(d[3])
        : "r"(a[0]), "r"(a[1]), "r"(a[2]), "r"(a[3]),
          "r"(b[0]), "r"(b[1]));
}

// hop-GEMM tile body: O1[m0.., n0..] = relu(A@Bt^T + bias), fp16 out.
__device__ __forceinline__ void hop_gemm_tile(
        const __half* __restrict__ A, const __half* __restrict__ Bt,
        const float* __restrict__ bias, __half* __restrict__ O1,
        int m0, int n0, int M,
        __half (*As)[40], __half (*Bs)[40], int tid) {
    const int wid = tid >> 5;
    const int lane = tid & 31;
    const int gid = lane >> 2;
    const int tig = lane & 3;
    const int wm = wid & 3;
    const int wn = wid >> 2;

    float acc[2][8][4];
    #pragma unroll
    for (int i = 0; i < 2; i++)
        #pragma unroll
        for (int j = 0; j < 8; j++)
            #pragma unroll
            for (int q = 0; q < 4; q++) acc[i][j][q] = 0.f;

    for (int k0 = 0; k0 < FH; k0 += 32) {
        #pragma unroll
        for (int i = 0; i < 2; i++) {
            int id = tid + i * 256;
            int r  = id >> 2;
            int g  = id & 3;
            int gm = m0 + r;
            uint4 av = make_uint4(0u, 0u, 0u, 0u);
            if (gm < M)
                av = __ldg((const uint4*)(A + (size_t)gm * FH + k0 + g * 8));
            *(uint4*)&As[r][g * 8] = av;
        }
        #pragma unroll
        for (int i = 0; i < 2; i++) {
            int id = tid + i * 256;
            int r  = id >> 2;
            int g  = id & 3;
            *(uint4*)&Bs[r][g * 8] =
                __ldg((const uint4*)(Bt + (size_t)(n0 + r) * FH + k0 + g * 8));
        }
        __syncthreads();

        #pragma unroll
        for (int kk = 0; kk < 32; kk += 16) {
            uint32_t afr[2][4];
            #pragma unroll
            for (int mt = 0; mt < 2; mt++) {
                int r = wm * 32 + mt * 16 + gid;
                afr[mt][0] = *(const uint32_t*)&As[r    ][kk + tig * 2];
                afr[mt][1] = *(const uint32_t*)&As[r + 8][kk + tig * 2];
                afr[mt][2] = *(const uint32_t*)&As[r    ][kk + tig * 2 + 8];
                afr[mt][3] = *(const uint32_t*)&As[r + 8][kk + tig * 2 + 8];
            }
            uint32_t bfr[8][2];
            #pragma unroll
            for (int nt = 0; nt < 8; nt++) {
                int cc = wn * 64 + nt * 8 + gid;
                bfr[nt][0] = *(const uint32_t*)&Bs[cc][kk + tig * 2];
                bfr[nt][1] = *(const uint32_t*)&Bs[cc][kk + tig * 2 + 8];
            }
            #pragma unroll
            for (int mt = 0; mt < 2; mt++)
                #pragma unroll
                for (int nt = 0; nt < 8; nt++)
                    mma_f16(acc[mt][nt], afr[mt], bfr[nt]);
        }
        __syncthreads();
    }

    #pragma unroll
    for (int mt = 0; mt < 2; mt++) {
        #pragma unroll
        for (int hm = 0; hm < 2; hm++) {
            int r = m0 + wm * 32 + mt * 16 + hm * 8 + gid;
            if (r >= M) continue;
            #pragma unroll
            for (int nt = 0; nt < 8; nt++) {
                int c = n0 + wn * 64 + nt * 8 + tig * 2;
                float v0 = fmaxf(acc[mt][nt][hm * 2]     + __ldg(&bias[c]),     0.f);
                float v1 = fmaxf(acc[mt][nt][hm * 2 + 1] + __ldg(&bias[c + 1]), 0.f);
                *(__half2*)(O1 + (size_t)r * FH + c) = __floats2half2_rn(v0, v1);
            }
        }
    }
}

// standalone hop-GEMM over rows [row_off + by*128 ...)
__global__ __launch_bounds__(256, 2)
void hop_gemm_kernel(const __half* __restrict__ A, const __half* __restrict__ Bt,
                     const float* __restrict__ bias, __half* __restrict__ O1,
                     int row_off) {
    __shared__ __half As[128][40];
    __shared__ __half Bs[128][40];
    hop_gemm_tile(A, Bt, bias, O1, row_off + blockIdx.y * 128,
                  blockIdx.x * 128, NN, As, Bs, threadIdx.x);
}

// fused: every 9th block = gemmA tile (rows < NH1), others = spmmB (rows >= NH1)
__global__ __launch_bounds__(256, 2)
void fused_hop_kernel(const __half* __restrict__ hin,     // spmm gathers from hin
                      const float* __restrict__ A2,
                      const __half* __restrict__ Bt,
                      const float* __restrict__ bias,
                      __half* __restrict__ hout) {        // gemm writes hout
    __shared__ __half As[128][40];
    __shared__ __half Bs[128][40];
    int bid = blockIdx.x;
    if (bid % 9 == 4) {
        int g = bid / 9;                 // 0..781
        int m0 = (g >> 1) * 128;         // 391 m-tiles
        int n0 = (g & 1) * 128;
        hop_gemm_tile(g_t16, Bt, bias, hout, m0, n0, NH1, As, Bs, threadIdx.x);
    } else {
        int s = bid - bid / 9 - ((bid % 9) > 4 ? 1 : 0);
        if (s >= SPMM_B_BLKS) return;
        int row = NH1 + s * 8 + (threadIdx.x >> 5);
        if (row >= NN) return;
        spmm_row(hin, A2, row, threadIdx.x & 31);
    }
}

// ---------------- dense GEMM (first + final layers; R4-proven) ----------------
// MODE 0: relu(acc+bias) -> fp16 O1 AND O2 ; MODE 2: acc+bias -> fp32 OF
template <int MODE>
__global__ __launch_bounds__(256, 2)
void gemm_f16_kernel(const __half* __restrict__ A, const __half* __restrict__ Bt,
                     const float* __restrict__ bias, float* __restrict__ OF,
                     __half* __restrict__ O1, __half* __restrict__ O2,
                     int M, int K, int Nc) {
    __shared__ __half As[128][40];
    __shared__ __half Bs[128][40];

    const int tid = threadIdx.x;
    const int wid = tid >> 5;
    const int lane = tid & 31;
    const int gid = lane >> 2;
    const int tig = lane & 3;
    const int wm = wid & 3;
    const int wn = wid >> 2;
    const int m0 = blockIdx.y * 128;
    const int n0 = blockIdx.x * 128;

    float acc[2][8][4];
    #pragma unroll
    for (int i = 0; i < 2; i++)
        #pragma unroll
        for (int j = 0; j < 8; j++)
            #pragma unroll
            for (int q = 0; q < 4; q++) acc[i][j][q] = 0.f;

    for (int k0 = 0; k0 < K; k0 += 32) {
        #pragma unroll
        for (int i = 0; i < 2; i++) {
            int id = tid + i * 256;
            int r  = id >> 2;
            int g  = id & 3;
            int gm = m0 + r;
            uint4 av = make_uint4(0u, 0u, 0u, 0u);
            if (gm < M)
                av = __ldg((const uint4*)(A + (size_t)gm * K + k0 + g * 8));
            *(uint4*)&As[r][g * 8] = av;
        }
        #pragma unroll
        for (int i = 0; i < 2; i++) {
            int id = tid + i * 256;
            int r  = id >> 2;
            int g  = id & 3;
            int gn = n0 + r;
            uint4 bv = make_uint4(0u, 0u, 0u, 0u);
            if (gn < Nc)
                bv = __ldg((const uint4*)(Bt + (size_t)gn * K + k0 + g * 8));
            *(uint4*)&Bs[r][g * 8] = bv;
        }
        __syncthreads();

        #pragma unroll
        for (int kk = 0; kk < 32; kk += 16) {
            uint32_t afr[2][4];
            #pragma unroll
            for (int mt = 0; mt < 2; mt++) {
                int r = wm * 32 + mt * 16 + gid;
                afr[mt][0] = *(const uint32_t*)&As[r    ][kk + tig * 2];
                afr[mt][1] = *(const uint32_t*)&As[r + 8][kk + tig * 2];
                afr[mt][2] = *(const uint32_t*)&As[r    ][kk + tig * 2 + 8];
                afr[mt][3] = *(const uint32_t*)&As[r + 8][kk + tig * 2 + 8];
            }
            uint32_t bfr[8][2];
            #pragma unroll
            for (int nt = 0; nt < 8; nt++) {
                int cc = wn * 64 + nt * 8 + gid;
                bfr[nt][0] = *(const uint32_t*)&Bs[cc][kk + tig * 2];
                bfr[nt][1] = *(const uint32_t*)&Bs[cc][kk + tig * 2 + 8];
            }
            #pragma unroll
            for (int mt = 0; mt < 2; mt++)
                #pragma unroll
                for (int nt = 0; nt < 8; nt++)
                    mma_f16(acc[mt][nt], afr[mt], bfr[nt]);
        }
        __syncthreads();
    }

    #pragma unroll
    for (int mt = 0; mt < 2; mt++) {
        #pragma unroll
        for (int hm = 0; hm < 2; hm++) {
            int r = m0 + wm * 32 + mt * 16 + hm * 8 + gid;
            if (r >= M) continue;
            #pragma unroll
            for (int nt = 0; nt < 8; nt++) {
                int c = n0 + wn * 64 + nt * 8 + tig * 2;
                if (c >= Nc) continue;
                float v0 = acc[mt][nt][hm * 2]     + __ldg(&bias[c]);
                float v1 = acc[mt][nt][hm * 2 + 1] + __ldg(&bias[c + 1]);
                if (MODE != 2) {
                    v0 = fmaxf(v0, 0.f); v1 = fmaxf(v1, 0.f);
                    __half2 hv = __floats2half2_rn(v0, v1);
                    *(__half2*)(O1 + (size_t)r * Nc + c) = hv;
                    if (MODE == 0)
                        *(__half2*)(O2 + (size_t)r * Nc + c) = hv;
                } else {
                    float* op = OF + (size_t)r * Nc + c;
                    op[0] = v0; op[1] = v1;
                }
            }
        }
    }
}

// ---------------- launch ------------------------------------------------------
extern "C" void kernel_launch(void* const* d_in, const int* in_sizes, int n_in,
                              void* d_out, int out_size) {
    const float* x    = (const float*)d_in[0];
    const int*   erow = (const int*)  d_in[1];
    const int*   ecol = (const int*)  d_in[2];
    const float* eval = (const float*)d_in[3];
    const float* A2   = (const float*)d_in[4];
    const float* W1   = (const float*)d_in[5];
    const float* b1   = (const float*)d_in[6];
    const float* W3   = (const float*)d_in[7];
    const float* b3   = (const float*)d_in[8];
    const float* W2   = (const float*)d_in[9];
    const float* b2   = (const float*)d_in[10];
    float* out = (float*)d_out;

    __half *px16, *px016, *ph16, *pg16, *pt16, *pW1t, *pW3p, *pW2t;
    cudaGetSymbolAddress((void**)&px16,  g_x16);
    cudaGetSymbolAddress((void**)&px016, g_x016);
    cudaGetSymbolAddress((void**)&ph16,  g_h16);
    cudaGetSymbolAddress((void**)&pg16,  g_g16);
    cudaGetSymbolAddress((void**)&pt16,  g_t16);
    cudaGetSymbolAddress((void**)&pW1t,  g_W1t);
    cudaGetSymbolAddress((void**)&pW3p,  g_W3p);
    cudaGetSymbolAddress((void**)&pW2t,  g_W2t);

    // ---- conversions ----
    x2h_kernel<<<(int)(((size_t)NN * FIN / 8 + 255) / 256), 256>>>(x);
    wt_kernel<<<(FIN * FH + 255) / 256, 256>>>(W1, pW1t, FIN, FH, 0);
    wt_kernel<<<(FH * FH + 255) / 256, 256>>>(W3, pW3p, FH, FH, 1);
    wt_kernel<<<(FH * FOUT + 255) / 256, 256>>>(W2, pW2t, FH, FOUT, 0);

    // ---- CSR build ----
    zero_cnt_kernel<<<(NN + 255) / 256, 256>>>();
    hist_kernel<<<(EE + 255) / 256, 256>>>(erow);
    scan_kernel<<<1, 1024>>>();
    scatter_kernel<<<(EE + 255) / 256, 256>>>(erow, ecol, eval);

    // ---- x0 = relu(x @ W1 + b1) -> h16 and x016 ----
    dim3 grid1((FH + 127) / 128, (NN + 127) / 128);
    gemm_f16_kernel<0><<<grid1, 256>>>(px16, pW1t, b1, nullptr, ph16, px016,
                                       NN, FIN, FH);

    // ---- 10 pipelined hops (ping-pong h) ----
    __half* hcur = ph16;
    __half* hnxt = pg16;
    dim3 gridB(2, (NN - NH1 + 127) / 128);
    for (int i = 0; i < HOPS; i++) {
        // spmm half A: rows [0, NH1)
        spmm_kernel<<<NH1 / 8, 256>>>(hcur, A2, 0, NH1);
        // fused: gemm half A (t->hnxt) interleaved with spmm half B (hcur->t)
        fused_hop_kernel<<<FUSED_GRID, 256>>>(hcur, A2, pW3p, b3, hnxt);
        // gemm half B
        hop_gemm_kernel<<<gridB, 256>>>(pt16, pW3p, b3, hnxt, NH1);
        __half* t = hcur; hcur = hnxt; hnxt = t;
    }

    // ---- out = h @ W2 + b2 ----
    dim3 grid2((FOUT + 127) / 128, (NN + 127) / 128);
    gemm_f16_kernel<2><<<grid2, 256>>>(hcur, pW2t, b2, out, nullptr,
                                       nullptr, NN, FH, FOUT);
}

// round 12
// speedup vs baseline: 1.5232x; 1.5232x over previous
#include <cuda_runtime.h>
#include <cuda_fp16.h>
#include <cstdint>

#define NN   100000
#define EE   3200000
#define FH   256
#define FIN  512
#define FOUT 64
#define HOPS 10

// ---------------- scratch (device globals) ----------------------------------
__device__ __half g_x016[(size_t)NN * FH];
__device__ __half g_h16 [(size_t)NN * FH];
__device__ __half g_t16 [(size_t)NN * FH];
__device__ __half g_W1t [(size_t)FIN * FH];
__device__ __half g_W3p [(size_t)FH * FH];   // (W3 + I)^T, [n][k]
__device__ __half g_W2t [(size_t)FH * FOUT];
__device__ int    g_rowstart[NN + 1];
__device__ int    g_cnt[NN];
__device__ int2   g_epack[EE];

// ---------------- weight transpose/convert ------------------------------------
__global__ void wt_kernel(const float* __restrict__ W, __half* __restrict__ Bt,
                          int K, int Nc, int addI) {
    int i = blockIdx.x * blockDim.x + threadIdx.x;
    if (i >= K * Nc) return;
    int n = i / K, k = i % K;
    float v = __ldg(&W[(size_t)k * Nc + n]);
    if (addI && k == n) v += 1.0f;
    Bt[i] = __float2half_rn(v);
}

// ---------------- CSR build --------------------------------------------------
__global__ void zero_cnt_kernel() {
    int i = blockIdx.x * blockDim.x + threadIdx.x;
    if (i < NN) g_cnt[i] = 0;
}

__global__ void hist_kernel(const int* __restrict__ erow) {
    int e = blockIdx.x * blockDim.x + threadIdx.x;
    if (e < EE) atomicAdd(&g_cnt[erow[e]], 1);
}

// exclusive scan; seeds g_cnt with offsets (scatter cursor)
__global__ void scan_kernel() {
    __shared__ int wsum[32];
    __shared__ int carry_s;
    int t = threadIdx.x, lane = t & 31, w = t >> 5;
    if (t == 0) carry_s = 0;
    __syncthreads();
    for (int base = 0; base < NN; base += 1024) {
        int i = base + t;
        int v = (i < NN) ? g_cnt[i] : 0;
        int s = v;
        #pragma unroll
        for (int off = 1; off < 32; off <<= 1) {
            int u = __shfl_up_sync(0xffffffff, s, off);
            if (lane >= off) s += u;
        }
        if (lane == 31) wsum[w] = s;
        __syncthreads();
        if (w == 0) {
            int ws = wsum[lane];
            #pragma unroll
            for (int off = 1; off < 32; off <<= 1) {
                int u = __shfl_up_sync(0xffffffff, ws, off);
                if (lane >= off) ws += u;
            }
            wsum[lane] = ws;
        }
        __syncthreads();
        int wpre = (w == 0) ? 0 : wsum[w - 1];
        if (i < NN) {
            int rs = carry_s + wpre + s - v;
            g_rowstart[i] = rs;
            g_cnt[i] = rs;          // scatter cursor
        }
        __syncthreads();
        if (t == 1023) carry_s += wsum[31];
        __syncthreads();
    }
    if (threadIdx.x == 0) g_rowstart[NN] = carry_s;
}

__global__ void scatter_kernel(const int* __restrict__ erow,
                               const int* __restrict__ ecol,
                               const float* __restrict__ eval) {
    int e = blockIdx.x * blockDim.x + threadIdx.x;
    if (e < EE) {
        int p = atomicAdd(&g_cnt[erow[e]], 1);
        g_epack[p] = make_int2(ecol[e], __float_as_int(eval[e]));
    }
}

// ---------------- SPMM: t16[row,:] = sum val*h16[col,:] + A2[row]*x016[row,:]
__global__ void spmm_kernel(const __half* __restrict__ h,
                            const float* __restrict__ A2) {
    int row  = blockIdx.x * 8 + (threadIdx.x >> 5);
    int lane = threadIdx.x & 31;
    if (row >= NN) return;
    int s = g_rowstart[row];
    int e = g_rowstart[row + 1];
    float acc[8];
    #pragma unroll
    for (int q = 0; q < 8; q++) acc[q] = 0.f;

    #pragma unroll 2
    for (int p = s; p < e; ++p) {
        int2 ev = __ldg(&g_epack[p]);
        float v = __int_as_float(ev.y);
        uint4 raw = __ldg(((const uint4*)(h + (size_t)ev.x * FH)) + lane);
        const __half2* hh = (const __half2*)&raw;
        #pragma unroll
        for (int q = 0; q < 4; q++) {
            float2 f = __half22float2(hh[q]);
            acc[2 * q]     += v * f.x;
            acc[2 * q + 1] += v * f.y;
        }
    }
    float a = __ldg(&A2[row]);
    uint4 xraw = __ldg(((const uint4*)(g_x016 + (size_t)row * FH)) + lane);
    const __half2* xh = (const __half2*)&xraw;
    #pragma unroll
    for (int q = 0; q < 4; q++) {
        float2 f = __half22float2(xh[q]);
        acc[2 * q]     += a * f.x;
        acc[2 * q + 1] += a * f.y;
    }
    uint4 o;
    #pragma unroll
    for (int q = 0; q < 4; q++)
        ((__half2*)&o)[q] = __floats2half2_rn(acc[2 * q], acc[2 * q + 1]);
    ((uint4*)(g_t16 + (size_t)row * FH))[lane] = o;
}

// ---------------- fp16 mma.sync GEMM (R4-proven) -------------------------------
// MODE 0 (TA=float): relu(acc+bias) -> fp16 O1 AND O2   (first layer, fp32 A)
// MODE 1 (TA=half) : relu(acc+bias) -> fp16 O1          (hop layer)
// MODE 2 (TA=half) : acc+bias       -> fp32 OF          (final layer)
__device__ __forceinline__ void mma_f16(float* d, const uint32_t* a, const uint32_t* b) {
    asm volatile(
        "mma.sync.aligned.m16n8k16.row.col.f32.f16.f16.f32 "
        "{%0,%1,%2,%3}, {%4,%5,%6,%7}, {%8,%9}, {%0,%1,%2,%3};\n"
        : "+f"(d[0]), "+f"(d[1]), "+f"(d[2]), "+f"(d[3])
        : "r"(a[0]), "r"(a[1]), "r"(a[2]), "r"(a[3]),
          "r"(b[0]), "r"(b[1]));
}

template <int MODE, typename TA>
__global__ __launch_bounds__(256, 2)
void gemm_f16_kernel(const TA* __restrict__ A, const __half* __restrict__ Bt,
                     const float* __restrict__ bias, float* __restrict__ OF,
                     __half* __restrict__ O1, __half* __restrict__ O2,
                     int M, int K, int Nc) {
    __shared__ __half As[128][40];
    __shared__ __half Bs[128][40];

    const int tid = threadIdx.x;
    const int wid = tid >> 5;
    const int lane = tid & 31;
    const int gid = lane >> 2;
    const int tig = lane & 3;
    const int wm = wid & 3;
    const int wn = wid >> 2;
    const int m0 = blockIdx.y * 128;
    const int n0 = blockIdx.x * 128;

    float acc[2][8][4];
    #pragma unroll
    for (int i = 0; i < 2; i++)
        #pragma unroll
        for (int j = 0; j < 8; j++)
            #pragma unroll
            for (int q = 0; q < 4; q++) acc[i][j][q] = 0.f;

    for (int k0 = 0; k0 < K; k0 += 32) {
        // ---- stage A tile (128 x 32 halves) ----
        if (sizeof(TA) == 2) {
            const __half* Ah = (const __half*)A;
            #pragma unroll
            for (int i = 0; i < 2; i++) {
                int id = tid + i * 256;
                int r  = id >> 2;
                int g  = id & 3;
                int gm = m0 + r;
                uint4 av = make_uint4(0u, 0u, 0u, 0u);
                if (gm < M)
                    av = __ldg((const uint4*)(Ah + (size_t)gm * K + k0 + g * 8));
                *(uint4*)&As[r][g * 8] = av;
            }
        } else {
            const float* Af = (const float*)A;
            #pragma unroll
            for (int i = 0; i < 4; i++) {
                int id = tid + i * 256;       // 0..1023
                int r  = id >> 3;             // 0..127
                int c4 = id & 7;              // float4 group (4 floats)
                int gm = m0 + r;
                float4 av = make_float4(0.f, 0.f, 0.f, 0.f);
                if (gm < M)
                    av = __ldg((const float4*)(Af + (size_t)gm * K + k0 + c4 * 4));
                __half2 h0 = __floats2half2_rn(av.x, av.y);
                __half2 h1 = __floats2half2_rn(av.z, av.w);
                *(__half2*)&As[r][c4 * 4]     = h0;
                *(__half2*)&As[r][c4 * 4 + 2] = h1;
            }
        }
        // ---- stage B tile (128 n-rows x 32 k) ----
        #pragma unroll
        for (int i = 0; i < 2; i++) {
            int id = tid + i * 256;
            int r  = id >> 2;
            int g  = id & 3;
            int gn = n0 + r;
            uint4 bv = make_uint4(0u, 0u, 0u, 0u);
            if (gn < Nc)
                bv = __ldg((const uint4*)(Bt + (size_t)gn * K + k0 + g * 8));
            *(uint4*)&Bs[r][g * 8] = bv;
        }
        __syncthreads();

        #pragma unroll
        for (int kk = 0; kk < 32; kk += 16) {
            uint32_t afr[2][4];
            #pragma unroll
            for (int mt = 0; mt < 2; mt++) {
                int r = wm * 32 + mt * 16 + gid;
                afr[mt][0] = *(const uint32_t*)&As[r    ][kk + tig * 2];
                afr[mt][1] = *(const uint32_t*)&As[r + 8][kk + tig * 2];
                afr[mt][2] = *(const uint32_t*)&As[r    ][kk + tig * 2 + 8];
                afr[mt][3] = *(const uint32_t*)&As[r + 8][kk + tig * 2 + 8];
            }
            uint32_t bfr[8][2];
            #pragma unroll
            for (int nt = 0; nt < 8; nt++) {
                int cc = wn * 64 + nt * 8 + gid;
                bfr[nt][0] = *(const uint32_t*)&Bs[cc][kk + tig * 2];
                bfr[nt][1] = *(const uint32_t*)&Bs[cc][kk + tig * 2 + 8];
            }
            #pragma unroll
            for (int mt = 0; mt < 2; mt++)
                #pragma unroll
                for (int nt = 0; nt < 8; nt++)
                    mma_f16(acc[mt][nt], afr[mt], bfr[nt]);
        }
        __syncthreads();
    }

    #pragma unroll
    for (int mt = 0; mt < 2; mt++) {
        #pragma unroll
        for (int hm = 0; hm < 2; hm++) {
            int r = m0 + wm * 32 + mt * 16 + hm * 8 + gid;
            if (r >= M) continue;
            #pragma unroll
            for (int nt = 0; nt < 8; nt++) {
                int c = n0 + wn * 64 + nt * 8 + tig * 2;
                if (c >= Nc) continue;
                float v0 = acc[mt][nt][hm * 2]     + __ldg(&bias[c]);
                float v1 = acc[mt][nt][hm * 2 + 1] + __ldg(&bias[c + 1]);
                if (MODE != 2) {
                    v0 = fmaxf(v0, 0.f); v1 = fmaxf(v1, 0.f);
                    __half2 hv = __floats2half2_rn(v0, v1);
                    *(__half2*)(O1 + (size_t)r * Nc + c) = hv;
                    if (MODE == 0)
                        *(__half2*)(O2 + (size_t)r * Nc + c) = hv;
                } else {
                    float* op = OF + (size_t)r * Nc + c;
                    op[0] = v0; op[1] = v1;
                }
            }
        }
    }
}

// ---------------- launch ------------------------------------------------------
extern "C" void kernel_launch(void* const* d_in, const int* in_sizes, int n_in,
                              void* d_out, int out_size) {
    const float* x    = (const float*)d_in[0];
    const int*   erow = (const int*)  d_in[1];
    const int*   ecol = (const int*)  d_in[2];
    const float* eval = (const float*)d_in[3];
    const float* A2   = (const float*)d_in[4];
    const float* W1   = (const float*)d_in[5];
    const float* b1   = (const float*)d_in[6];
    const float* W3   = (const float*)d_in[7];
    const float* b3   = (const float*)d_in[8];
    const float* W2   = (const float*)d_in[9];
    const float* b2   = (const float*)d_in[10];
    float* out = (float*)d_out;

    __half *px016, *ph16, *pt16, *pW1t, *pW3p, *pW2t;
    cudaGetSymbolAddress((void**)&px016, g_x016);
    cudaGetSymbolAddress((void**)&ph16,  g_h16);
    cudaGetSymbolAddress((void**)&pt16,  g_t16);
    cudaGetSymbolAddress((void**)&pW1t,  g_W1t);
    cudaGetSymbolAddress((void**)&pW3p,  g_W3p);
    cudaGetSymbolAddress((void**)&pW2t,  g_W2t);

    // ---- weight conversions ----
    wt_kernel<<<(FIN * FH + 255) / 256, 256>>>(W1, pW1t, FIN, FH, 0);
    wt_kernel<<<(FH * FH + 255) / 256, 256>>>(W3, pW3p, FH, FH, 1);
    wt_kernel<<<(FH * FOUT + 255) / 256, 256>>>(W2, pW2t, FH, FOUT, 0);

    // ---- CSR build (single zero pass; scan seeds scatter cursor) ----
    zero_cnt_kernel<<<(NN + 255) / 256, 256>>>();
    hist_kernel<<<(EE + 255) / 256, 256>>>(erow);
    scan_kernel<<<1, 1024>>>();
    scatter_kernel<<<(EE + 255) / 256, 256>>>(erow, ecol, eval);

    // ---- x0 = relu(x @ W1 + b1) -> h16 and x016  (fp32 A, in-kernel convert) ----
    dim3 grid1((FH + 127) / 128, (NN + 127) / 128);
    gemm_f16_kernel<0, float><<<grid1, 256>>>(x, pW1t, b1, nullptr, ph16, px016,
                                              NN, FIN, FH);

    // ---- 10 hops: t16 = spmm(h16) ; h16 = relu(t16 @ (W3+I) + b3) ----
    dim3 grid3((FH + 127) / 128, (NN + 127) / 128);
    for (int i = 0; i < HOPS; i++) {
        spmm_kernel<<<(NN + 7) / 8, 256>>>(ph16, A2);
        gemm_f16_kernel<1, __half><<<grid3, 256>>>(pt16, pW3p, b3, nullptr,
                                                   ph16, nullptr, NN, FH, FH);
    }

    // ---- out = h16 @ W2 + b2 ----
    dim3 grid2((FOUT + 127) / 128, (NN + 127) / 128);
    gemm_f16_kernel<2, __half><<<grid2, 256>>>(ph16, pW2t, b2, out, nullptr,
                                               nullptr, NN, FH, FOUT);
}

// round 13
// speedup vs baseline: 1.5703x; 1.0309x over previous
#include <cuda_runtime.h>
#include <cuda_fp16.h>
#include <cstdint>

#define NN   100000
#define EE   3200000
#define FH   256
#define FIN  512
#define FOUT 64
#define HOPS 10
#define SCAN_BLK 1024
#define NBLK ((NN + SCAN_BLK - 1) / SCAN_BLK)   // 98

// ---------------- scratch (device globals) ----------------------------------
__device__ __half g_x016[(size_t)NN * FH];
__device__ __half g_h16 [(size_t)NN * FH];
__device__ __half g_t16 [(size_t)NN * FH];
__device__ __half g_W1t [(size_t)FIN * FH];
__device__ __half g_W3p [(size_t)FH * FH];   // (W3 + I)^T, [n][k]
__device__ __half g_W2t [(size_t)FH * FOUT];
__device__ int    g_rowstart[NN + 1];
__device__ int    g_cnt[NN];
__device__ int    g_bsum[NBLK];
__device__ int2   g_epack[EE];

// ---------------- weight transpose/convert ------------------------------------
__global__ void wt_kernel(const float* __restrict__ W, __half* __restrict__ Bt,
                          int K, int Nc, int addI) {
    int i = blockIdx.x * blockDim.x + threadIdx.x;
    if (i >= K * Nc) return;
    int n = i / K, k = i % K;
    float v = __ldg(&W[(size_t)k * Nc + n]);
    if (addI && k == n) v += 1.0f;
    Bt[i] = __float2half_rn(v);
}

// ---------------- CSR build --------------------------------------------------
__global__ void zero_cnt_kernel() {
    int i = blockIdx.x * blockDim.x + threadIdx.x;
    if (i < NN) g_cnt[i] = 0;
}

__global__ void hist_kernel(const int* __restrict__ erow) {
    int e = blockIdx.x * blockDim.x + threadIdx.x;
    if (e < EE) atomicAdd(&g_cnt[erow[e]], 1);
}

// hierarchical scan, stage 1: per-block exclusive scan + block sums
__global__ void scan1_kernel() {
    __shared__ int wsum[32];
    int t = threadIdx.x, lane = t & 31, w = t >> 5;
    int i = blockIdx.x * SCAN_BLK + t;
    int v = (i < NN) ? g_cnt[i] : 0;
    int s = v;
    #pragma unroll
    for (int off = 1; off < 32; off <<= 1) {
        int u = __shfl_up_sync(0xffffffff, s, off);
        if (lane >= off) s += u;
    }
    if (lane == 31) wsum[w] = s;
    __syncthreads();
    if (w == 0) {
        int ws = wsum[lane];
        #pragma unroll
        for (int off = 1; off < 32; off <<= 1) {
            int u = __shfl_up_sync(0xffffffff, ws, off);
            if (lane >= off) ws += u;
        }
        wsum[lane] = ws;
    }
    __syncthreads();
    int wpre = (w == 0) ? 0 : wsum[w - 1];
    if (i < NN) g_rowstart[i] = wpre + s - v;   // block-local exclusive
    if (t == SCAN_BLK - 1) g_bsum[blockIdx.x] = wsum[31];
}

// stage 2: one block scans the 98 block sums (exclusive, in place) + total
__global__ void scan2_kernel() {
    __shared__ int wsum[32];
    int t = threadIdx.x, lane = t & 31, w = t >> 5;   // 128 threads, 4 warps
    int v = (t < NBLK) ? g_bsum[t] : 0;
    int s = v;
    #pragma unroll
    for (int off = 1; off < 32; off <<= 1) {
        int u = __shfl_up_sync(0xffffffff, s, off);
        if (lane >= off) s += u;
    }
    if (lane == 31) wsum[w] = s;
    __syncthreads();
    if (w == 0 && lane < 4) {
        int ws = wsum[lane];
        #pragma unroll
        for (int off = 1; off < 4; off <<= 1) {
            int u = __shfl_up_sync(0xf, ws, off);
            if (lane >= off) ws += u;
        }
        wsum[lane] = ws;
    }
    __syncthreads();
    int wpre = (w == 0) ? 0 : wsum[w - 1];
    if (t < NBLK) g_bsum[t] = wpre + s - v;          // exclusive
    if (t == 127) g_rowstart[NN] = wsum[3];          // grand total
}

// stage 3: add block offsets; seed scatter cursor
__global__ void scan3_kernel() {
    int i = blockIdx.x * SCAN_BLK + threadIdx.x;
    if (i < NN) {
        int rs = g_rowstart[i] + g_bsum[blockIdx.x];
        g_rowstart[i] = rs;
        g_cnt[i] = rs;
    }
}

__global__ void scatter_kernel(const int* __restrict__ erow,
                               const int* __restrict__ ecol,
                               const float* __restrict__ eval) {
    int e = blockIdx.x * blockDim.x + threadIdx.x;
    if (e < EE) {
        int p = atomicAdd(&g_cnt[erow[e]], 1);
        g_epack[p] = make_int2(ecol[e], __float_as_int(eval[e]));
    }
}

// ---------------- SPMM: t16[row,:] = sum val*h16[col,:] + A2[row]*x016[row,:]
__global__ void spmm_kernel(const __half* __restrict__ h,
                            const float* __restrict__ A2) {
    int row  = blockIdx.x * 8 + (threadIdx.x >> 5);
    int lane = threadIdx.x & 31;
    if (row >= NN) return;
    int s = g_rowstart[row];
    int e = g_rowstart[row + 1];
    float acc[8];
    #pragma unroll
    for (int q = 0; q < 8; q++) acc[q] = 0.f;

    #pragma unroll 2
    for (int p = s; p < e; ++p) {
        int2 ev = __ldg(&g_epack[p]);
        float v = __int_as_float(ev.y);
        uint4 raw = __ldg(((const uint4*)(h + (size_t)ev.x * FH)) + lane);
        const __half2* hh = (const __half2*)&raw;
        #pragma unroll
        for (int q = 0; q < 4; q++) {
            float2 f = __half22float2(hh[q]);
            acc[2 * q]     += v * f.x;
            acc[2 * q + 1] += v * f.y;
        }
    }
    float a = __ldg(&A2[row]);
    uint4 xraw = __ldg(((const uint4*)(g_x016 + (size_t)row * FH)) + lane);
    const __half2* xh = (const __half2*)&xraw;
    #pragma unroll
    for (int q = 0; q < 4; q++) {
        float2 f = __half22float2(xh[q]);
        acc[2 * q]     += a * f.x;
        acc[2 * q + 1] += a * f.y;
    }
    uint4 o;
    #pragma unroll
    for (int q = 0; q < 4; q++)
        ((__half2*)&o)[q] = __floats2half2_rn(acc[2 * q], acc[2 * q + 1]);
    ((uint4*)(g_t16 + (size_t)row * FH))[lane] = o;
}

// ---------------- fp16 mma.sync GEMM (R12-proven) ------------------------------
// MODE 0 (TA=float): relu(acc+bias) -> fp16 O1 AND O2   (first layer, fp32 A)
// MODE 1 (TA=half) : relu(acc+bias) -> fp16 O1          (hop layer)
// MODE 2 (TA=half) : acc+bias       -> fp32 OF          (final layer)
__device__ __forceinline__ void mma_f16(float* d, const uint32_t* a, const uint32_t* b) {
    asm volatile(
        "mma.sync.aligned.m16n8k16.row.col.f32.f16.f16.f32 "
        "{%0,%1,%2,%3}, {%4,%5,%6,%7}, {%8,%9}, {%0,%1,%2,%3};\n"
        : "+f"(d[0]), "+f"(d[1]), "+f"(d[2]), "+f"(d[3])
        : "r"(a[0]), "r"(a[1]), "r"(a[2]), "r"(a[3]),
          "r"(b[0]), "r"(b[1]));
}

template <int MODE, typename TA>
__global__ __launch_bounds__(256, 2)
void gemm_f16_kernel(const TA* __restrict__ A, const __half* __restrict__ Bt,
                     const float* __restrict__ bias, float* __restrict__ OF,
                     __half* __restrict__ O1, __half* __restrict__ O2,
                     int M, int K, int Nc) {
    __shared__ __half As[128][40];
    __shared__ __half Bs[128][40];

    const int tid = threadIdx.x;
    const int wid = tid >> 5;
    const int lane = tid & 31;
    const int gid = lane >> 2;
    const int tig = lane & 3;
    const int wm = wid & 3;
    const int wn = wid >> 2;
    const int m0 = blockIdx.y * 128;
    const int n0 = blockIdx.x * 128;

    float acc[2][8][4];
    #pragma unroll
    for (int i = 0; i < 2; i++)
        #pragma unroll
        for (int j = 0; j < 8; j++)
            #pragma unroll
            for (int q = 0; q < 4; q++) acc[i][j][q] = 0.f;

    for (int k0 = 0; k0 < K; k0 += 32) {
        // ---- stage A tile (128 x 32 halves) ----
        if (sizeof(TA) == 2) {
            const __half* Ah = (const __half*)A;
            #pragma unroll
            for (int i = 0; i < 2; i++) {
                int id = tid + i * 256;
                int r  = id >> 2;
                int g  = id & 3;
                int gm = m0 + r;
                uint4 av = make_uint4(0u, 0u, 0u, 0u);
                if (gm < M)
                    av = __ldg((const uint4*)(Ah + (size_t)gm * K + k0 + g * 8));
                *(uint4*)&As[r][g * 8] = av;
            }
        } else {
            const float* Af = (const float*)A;
            #pragma unroll
            for (int i = 0; i < 4; i++) {
                int id = tid + i * 256;       // 0..1023
                int r  = id >> 3;             // 0..127
                int c4 = id & 7;              // float4 group (4 floats)
                int gm = m0 + r;
                float4 av = make_float4(0.f, 0.f, 0.f, 0.f);
                if (gm < M)
                    av = __ldg((const float4*)(Af + (size_t)gm * K + k0 + c4 * 4));
                __half2 h0 = __floats2half2_rn(av.x, av.y);
                __half2 h1 = __floats2half2_rn(av.z, av.w);
                *(__half2*)&As[r][c4 * 4]     = h0;
                *(__half2*)&As[r][c4 * 4 + 2] = h1;
            }
        }
        // ---- stage B tile (128 n-rows x 32 k) ----
        #pragma unroll
        for (int i = 0; i < 2; i++) {
            int id = tid + i * 256;
            int r  = id >> 2;
            int g  = id & 3;
            int gn = n0 + r;
            uint4 bv = make_uint4(0u, 0u, 0u, 0u);
            if (gn < Nc)
                bv = __ldg((const uint4*)(Bt + (size_t)gn * K + k0 + g * 8));
            *(uint4*)&Bs[r][g * 8] = bv;
        }
        __syncthreads();

        #pragma unroll
        for (int kk = 0; kk < 32; kk += 16) {
            uint32_t afr[2][4];
            #pragma unroll
            for (int mt = 0; mt < 2; mt++) {
                int r = wm * 32 + mt * 16 + gid;
                afr[mt][0] = *(const uint32_t*)&As[r    ][kk + tig * 2];
                afr[mt][1] = *(const uint32_t*)&As[r + 8][kk + tig * 2];
                afr[mt][2] = *(const uint32_t*)&As[r    ][kk + tig * 2 + 8];
                afr[mt][3] = *(const uint32_t*)&As[r + 8][kk + tig * 2 + 8];
            }
            uint32_t bfr[8][2];
            #pragma unroll
            for (int nt = 0; nt < 8; nt++) {
                int cc = wn * 64 + nt * 8 + gid;
                bfr[nt][0] = *(const uint32_t*)&Bs[cc][kk + tig * 2];
                bfr[nt][1] = *(const uint32_t*)&Bs[cc][kk + tig * 2 + 8];
            }
            #pragma unroll
            for (int mt = 0; mt < 2; mt++)
                #pragma unroll
                for (int nt = 0; nt < 8; nt++)
                    mma_f16(acc[mt][nt], afr[mt], bfr[nt]);
        }
        __syncthreads();
    }

    #pragma unroll
    for (int mt = 0; mt < 2; mt++) {
        #pragma unroll
        for (int hm = 0; hm < 2; hm++) {
            int r = m0 + wm * 32 + mt * 16 + hm * 8 + gid;
            if (r >= M) continue;
            #pragma unroll
            for (int nt = 0; nt < 8; nt++) {
                int c = n0 + wn * 64 + nt * 8 + tig * 2;
                if (c >= Nc) continue;
                float v0 = acc[mt][nt][hm * 2]     + __ldg(&bias[c]);
                float v1 = acc[mt][nt][hm * 2 + 1] + __ldg(&bias[c + 1]);
                if (MODE != 2) {
                    v0 = fmaxf(v0, 0.f); v1 = fmaxf(v1, 0.f);
                    __half2 hv = __floats2half2_rn(v0, v1);
                    *(__half2*)(O1 + (size_t)r * Nc + c) = hv;
                    if (MODE == 0)
                        *(__half2*)(O2 + (size_t)r * Nc + c) = hv;
                } else {
                    float* op = OF + (size_t)r * Nc + c;
                    op[0] = v0; op[1] = v1;
                }
            }
        }
    }
}

// ---------------- launch ------------------------------------------------------
extern "C" void kernel_launch(void* const* d_in, const int* in_sizes, int n_in,
                              void* d_out, int out_size) {
    const float* x    = (const float*)d_in[0];
    const int*   erow = (const int*)  d_in[1];
    const int*   ecol = (const int*)  d_in[2];
    const float* eval = (const float*)d_in[3];
    const float* A2   = (const float*)d_in[4];
    const float* W1   = (const float*)d_in[5];
    const float* b1   = (const float*)d_in[6];
    const float* W3   = (const float*)d_in[7];
    const float* b3   = (const float*)d_in[8];
    const float* W2   = (const float*)d_in[9];
    const float* b2   = (const float*)d_in[10];
    float* out = (float*)d_out;

    __half *px016, *ph16, *pt16, *pW1t, *pW3p, *pW2t;
    cudaGetSymbolAddress((void**)&px016, g_x016);
    cudaGetSymbolAddress((void**)&ph16,  g_h16);
    cudaGetSymbolAddress((void**)&pt16,  g_t16);
    cudaGetSymbolAddress((void**)&pW1t,  g_W1t);
    cudaGetSymbolAddress((void**)&pW3p,  g_W3p);
    cudaGetSymbolAddress((void**)&pW2t,  g_W2t);

    // ---- weight conversions ----
    wt_kernel<<<(FIN * FH + 255) / 256, 256>>>(W1, pW1t, FIN, FH, 0);
    wt_kernel<<<(FH * FH + 255) / 256, 256>>>(W3, pW3p, FH, FH, 1);
    wt_kernel<<<(FH * FOUT + 255) / 256, 256>>>(W2, pW2t, FH, FOUT, 0);

    // ---- CSR build (parallel hierarchical scan; scan seeds scatter cursor) ----
    zero_cnt_kernel<<<(NN + 255) / 256, 256>>>();
    hist_kernel<<<(EE + 255) / 256, 256>>>(erow);
    scan1_kernel<<<NBLK, SCAN_BLK>>>();
    scan2_kernel<<<1, 128>>>();
    scan3_kernel<<<NBLK, SCAN_BLK>>>();
    scatter_kernel<<<(EE + 255) / 256, 256>>>(erow, ecol, eval);

    // ---- x0 = relu(x @ W1 + b1) -> h16 and x016  (fp32 A, in-kernel convert) ----
    dim3 grid1((FH + 127) / 128, (NN + 127) / 128);
    gemm_f16_kernel<0, float><<<grid1, 256>>>(x, pW1t, b1, nullptr, ph16, px016,
                                              NN, FIN, FH);

    // ---- 10 hops: t16 = spmm(h16) ; h16 = relu(t16 @ (W3+I) + b3) ----
    dim3 grid3((FH + 127) / 128, (NN + 127) / 128);
    for (int i = 0; i < HOPS; i++) {
        spmm_kernel<<<(NN + 7) / 8, 256>>>(ph16, A2);
        gemm_f16_kernel<1, __half><<<grid3, 256>>>(pt16, pW3p, b3, nullptr,
                                                   ph16, nullptr, NN, FH, FH);
    }

    // ---- out = h16 @ W2 + b2 ----
    dim3 grid2((FOUT + 127) / 128, (NN + 127) / 128);
    gemm_f16_kernel<2, __half><<<grid2, 256>>>(ph16, pW2t, b2, out, nullptr,
                                               nullptr, NN, FH, FOUT);
}